// round 6
// baseline (speedup 1.0000x reference)
#include <cuda_runtime.h>
#include <cstdint>
#include <math.h>

#define Vv 32000
#define Hh 512
#define Bb 16
#define Ss 64
#define G3 1536   // 3H
#define K2 1024   // 2H
#define NCTA_GRU 128

// ---------------- scratch (static device allocations only) ----------------
__device__ __align__(16) float g_gi[Ss * Bb * G3];      // [s][b][3H]
__device__ __align__(16) float g_ys[Ss * Bb * Hh];      // [s][b][H]
__device__ __align__(16) float g_h[2][Bb * Hh];         // double-buffered h
__device__ unsigned long long g_slots[NCTA_GRU];        // barrier slots (monotonic)

__device__ __forceinline__ unsigned long long ld_slot(const unsigned long long* p) {
    unsigned long long v;
    asm volatile("ld.global.cg.u64 %0, [%1];" : "=l"(v) : "l"(p) : "memory");
    return v;
}

// L2-coherent vector load (bypasses L1 for cross-CTA h exchange).
__device__ __forceinline__ float4 ldcg4(const float* p) {
    float4 v;
    asm volatile("ld.global.cg.v4.f32 {%0,%1,%2,%3}, [%4];"
                 : "=f"(v.x), "=f"(v.y), "=f"(v.z), "=f"(v.w) : "l"(p));
    return v;
}

// TF32 rounding (mimics cublas/XLA default fp32-matmul input rounding).
// Products of two tf32 values are EXACT in fp32, so only accumulation order
// differs from the reference (~1e-7), not per-element input rounding (~1e-3).
__device__ __forceinline__ float tf32r(float x) {
    uint32_t u;
    asm("cvt.rna.tf32.f32 %0, %1;" : "=r"(u) : "f"(x));
    return __uint_as_float(u);
}
__device__ __forceinline__ float4 tf32r4(float4 v) {
    v.x = tf32r(v.x); v.y = tf32r(v.y); v.z = tf32r(v.z); v.w = tf32r(v.w);
    return v;
}

// ---------------- Kernel A: gi = concat(emb[tok], thought) @ W_ih^T + b_ih ----------------
// TF32-input semantics: both operands rounded at smem staging.
__global__ void __launch_bounds__(256) gi_gemm(const int* __restrict__ tseq,
                                               const float* __restrict__ thought,
                                               const float* __restrict__ emb,
                                               const float* __restrict__ W_ih,
                                               const float* __restrict__ b_ih) {
    __shared__ float sA[2][16][64];
    __shared__ float sB[2][16][64];
    const int tid = threadIdx.x;
    const int bm0 = blockIdx.x * 64, bn0 = blockIdx.y * 64;
    const int tx = tid & 15, ty = tid >> 4;
    const int la_m = tid >> 2, la_k = (tid & 3) * 4;

    const int am = bm0 + la_m;
    const int s_ = am >> 4, b_ = am & 15;           // row = s*16+b
    const int tok = tseq[b_ * Ss + s_];
    const float* __restrict__ arow0 = emb + (size_t)tok * Hh;
    const float* __restrict__ arow1 = thought + (size_t)b_ * Hh;
    const float* __restrict__ brow  = W_ih + (size_t)(bn0 + la_m) * K2 + la_k;

    float acc[4][4];
#pragma unroll
    for (int i = 0; i < 4; i++)
#pragma unroll
        for (int j = 0; j < 4; j++) acc[i][j] = 0.f;

    {
        int kg = la_k;
        float4 a4 = tf32r4((kg < Hh) ? *(const float4*)&arow0[kg] : *(const float4*)&arow1[kg - Hh]);
        float4 b4 = tf32r4(*(const float4*)&brow[0]);
        sA[0][la_k + 0][la_m] = a4.x; sA[0][la_k + 1][la_m] = a4.y;
        sA[0][la_k + 2][la_m] = a4.z; sA[0][la_k + 3][la_m] = a4.w;
        sB[0][la_k + 0][la_m] = b4.x; sB[0][la_k + 1][la_m] = b4.y;
        sB[0][la_k + 2][la_m] = b4.z; sB[0][la_k + 3][la_m] = b4.w;
    }
    __syncthreads();

    int buf = 0;
    const int NT = K2 / 16;  // 64
    for (int kt = 0; kt < NT; ++kt) {
        float4 na, nb;
        const bool more = (kt + 1 < NT);
        if (more) {
            int kg = (kt + 1) * 16 + la_k;
            na = (kg < Hh) ? *(const float4*)&arow0[kg] : *(const float4*)&arow1[kg - Hh];
            nb = *(const float4*)&brow[(kt + 1) * 16];
        }
#pragma unroll
        for (int k = 0; k < 16; k++) {
            float4 av = *(const float4*)&sA[buf][k][ty * 4];
            float4 bv = *(const float4*)&sB[buf][k][tx * 4];
            acc[0][0] = fmaf(av.x, bv.x, acc[0][0]); acc[0][1] = fmaf(av.x, bv.y, acc[0][1]);
            acc[0][2] = fmaf(av.x, bv.z, acc[0][2]); acc[0][3] = fmaf(av.x, bv.w, acc[0][3]);
            acc[1][0] = fmaf(av.y, bv.x, acc[1][0]); acc[1][1] = fmaf(av.y, bv.y, acc[1][1]);
            acc[1][2] = fmaf(av.y, bv.z, acc[1][2]); acc[1][3] = fmaf(av.y, bv.w, acc[1][3]);
            acc[2][0] = fmaf(av.z, bv.x, acc[2][0]); acc[2][1] = fmaf(av.z, bv.y, acc[2][1]);
            acc[2][2] = fmaf(av.z, bv.z, acc[2][2]); acc[2][3] = fmaf(av.z, bv.w, acc[2][3]);
            acc[3][0] = fmaf(av.w, bv.x, acc[3][0]); acc[3][1] = fmaf(av.w, bv.y, acc[3][1]);
            acc[3][2] = fmaf(av.w, bv.z, acc[3][2]); acc[3][3] = fmaf(av.w, bv.w, acc[3][3]);
        }
        if (more) {
            int nbuf = buf ^ 1;
            na = tf32r4(na); nb = tf32r4(nb);
            sA[nbuf][la_k + 0][la_m] = na.x; sA[nbuf][la_k + 1][la_m] = na.y;
            sA[nbuf][la_k + 2][la_m] = na.z; sA[nbuf][la_k + 3][la_m] = na.w;
            sB[nbuf][la_k + 0][la_m] = nb.x; sB[nbuf][la_k + 1][la_m] = nb.y;
            sB[nbuf][la_k + 2][la_m] = nb.z; sB[nbuf][la_k + 3][la_m] = nb.w;
            __syncthreads();
            buf = nbuf;
        }
    }

    const float4 bb = *(const float4*)&b_ih[bn0 + tx * 4];
#pragma unroll
    for (int i = 0; i < 4; i++) {
        float4 r;
        r.x = acc[i][0] + bb.x; r.y = acc[i][1] + bb.y;
        r.z = acc[i][2] + bb.z; r.w = acc[i][3] + bb.w;
        *(float4*)&g_gi[(size_t)(bm0 + ty * 4 + i) * G3 + bn0 + tx * 4] = r;
    }
}

// ---------------- Kernel B: persistent GRU over 64 steps ----------------
// h @ W_hh^T in TF32-input semantics: sW pre-rounded, h rounded in-register
// (cvt on ALU pipe overlaps the FMA pipe). Carried h stays full fp32.
__global__ void __launch_bounds__(256) gru_kernel(const float* __restrict__ hidden,
                                                  const float* __restrict__ W_hh,
                                                  const float* __restrict__ b_hh,
                                                  float* __restrict__ outH) {
    extern __shared__ float smem[];
    float* sW  = smem;                 // [3][4][512] = 6144 floats (tf32-rounded)
    float* sh  = smem + 6144;          // [16][516]   = 8256 floats (full fp32)
    float* red = smem + 6144 + 8256;   // [3][4][16][4] = 768 floats

    const int tid = threadIdx.x;
    const int cta = blockIdx.x;
    const int j0 = cta * 4;

    __shared__ unsigned long long sbase;
    if (tid == 0) sbase = g_slots[cta];

    for (int i = tid; i < 6144 / 4; i += 256) {
        int f = i * 4;
        int g = f >> 11; int jj = (f >> 9) & 3; int k = f & 511;
        float4 w = tf32r4(*(const float4*)&W_hh[(size_t)(g * Hh + j0 + jj) * Hh + k]);
        *(float4*)&sW[(g * 4 + jj) * 512 + k] = w;
    }
    __syncthreads();

    const int lane = tid & 31, wrp = tid >> 5;
    const int jj  = wrp & 3;
    const int ks  = (((wrp >> 2) << 1) | (lane >> 4));  // 0..3
    const int b   = lane & 15;
    const int kb  = ks * 128;
    const float* wr = &sW[(0 * 4 + jj) * 512];
    const float* wz = &sW[(1 * 4 + jj) * 512];
    const float* wn = &sW[(2 * 4 + jj) * 512];

    for (int s = 0; s < Ss; s++) {
        const float* hsrc = (s == 0) ? hidden : g_h[(s + 1) & 1];
        for (int i = tid; i < 2048; i += 256) {   // 8192 floats / 4
            int f = i * 4; int bb2 = f >> 9; int k = f & 511;
            float4 hv = ldcg4(&hsrc[bb2 * Hh + k]);
            *(float4*)&sh[bb2 * 516 + k] = hv;
        }
        __syncthreads();

        float ar = 0.f, az = 0.f, an = 0.f;
        const float* hb = &sh[b * 516];
#pragma unroll 8
        for (int k = kb; k < kb + 128; k += 4) {
            float4 hv = tf32r4(*(const float4*)&hb[k]);   // tf32 inputs, fp32 accum
            float4 r4 = *(const float4*)&wr[k];
            float4 z4 = *(const float4*)&wz[k];
            float4 n4 = *(const float4*)&wn[k];
            ar = fmaf(hv.x, r4.x, ar); ar = fmaf(hv.y, r4.y, ar);
            ar = fmaf(hv.z, r4.z, ar); ar = fmaf(hv.w, r4.w, ar);
            az = fmaf(hv.x, z4.x, az); az = fmaf(hv.y, z4.y, az);
            az = fmaf(hv.z, z4.z, az); az = fmaf(hv.w, z4.w, az);
            an = fmaf(hv.x, n4.x, an); an = fmaf(hv.y, n4.y, an);
            an = fmaf(hv.z, n4.z, an); an = fmaf(hv.w, n4.w, an);
        }
        red[((0 * 4 + jj) * 16 + b) * 4 + ks] = ar;
        red[((1 * 4 + jj) * 16 + b) * 4 + ks] = az;
        red[((2 * 4 + jj) * 16 + b) * 4 + ks] = an;
        __syncthreads();

        if (tid < 64) {
            const int jj2 = tid >> 4, b2 = tid & 15;
            const int col = j0 + jj2;
            float ghr = 0.f, ghz = 0.f, ghn = 0.f;
#pragma unroll
            for (int q = 0; q < 4; q++) {
                ghr += red[((0 * 4 + jj2) * 16 + b2) * 4 + q];
                ghz += red[((1 * 4 + jj2) * 16 + b2) * 4 + q];
                ghn += red[((2 * 4 + jj2) * 16 + b2) * 4 + q];
            }
            ghr += __ldg(&b_hh[col]); ghz += __ldg(&b_hh[Hh + col]); ghn += __ldg(&b_hh[2 * Hh + col]);
            const size_t gib = (size_t)(s * Bb + b2) * G3 + col;
            const float ir = g_gi[gib], iz = g_gi[gib + Hh], inn = g_gi[gib + 2 * Hh];
            const float r = 1.f / (1.f + expf(-(ir + ghr)));
            const float z = 1.f / (1.f + expf(-(iz + ghz)));
            const float n = tanhf(inn + r * ghn);
            const float ho = sh[b2 * 516 + col];     // full-precision carry
            const float hn = (1.f - z) * n + z * ho;
            g_h[s & 1][b2 * Hh + col] = hn;
            g_ys[(size_t)(s * Bb + b2) * Hh + col] = hn;
            if (s == Ss - 1) outH[b2 * Hh + col] = hn;
        }
        __syncthreads();

        if (s < Ss - 1) {
            const unsigned long long tgt = sbase + (unsigned long long)(s + 1);
            if (tid == 0) {
                __threadfence();
                ((volatile unsigned long long*)g_slots)[cta] = tgt;
            }
            if (tid < 32) {
                for (;;) {
                    bool ok = true;
#pragma unroll
                    for (int q = 0; q < 4; q++)
                        ok &= (ld_slot(&g_slots[lane + q * 32]) >= tgt);
                    if (ok) break;
                }
            }
            __syncthreads();
        }
    }
}

// ---------------- Kernel C: logits = ys @ W_out^T + b_out (exact fp32) ----------------
__global__ void __launch_bounds__(256) out_gemm(const float* __restrict__ W_out,
                                                const float* __restrict__ b_out,
                                                float* __restrict__ out) {
    __shared__ float sA[2][16][128];
    __shared__ float sB[2][16][128];
    const int tid = threadIdx.x;
    const int bn0 = blockIdx.x * 128, bm0 = blockIdx.y * 128;
    const int tx = tid & 15, ty = tid >> 4;
    const int la_r = tid >> 2, la_k = (tid & 3) * 4;

    const int am0 = bm0 + la_r;
    const int am1 = am0 + 64;
    const float* __restrict__ ap0 = g_ys + (size_t)((am0 & 63) * Bb + (am0 >> 6)) * Hh + la_k;
    const float* __restrict__ ap1 = g_ys + (size_t)((am1 & 63) * Bb + (am1 >> 6)) * Hh + la_k;
    const float* __restrict__ bp0 = W_out + (size_t)(bn0 + la_r) * Hh + la_k;
    const float* __restrict__ bp1 = W_out + (size_t)(bn0 + 64 + la_r) * Hh + la_k;

    float acc[8][8];
#pragma unroll
    for (int i = 0; i < 8; i++)
#pragma unroll
        for (int j = 0; j < 8; j++) acc[i][j] = 0.f;

    {
        float4 a0 = *(const float4*)&ap0[0];
        float4 a1 = *(const float4*)&ap1[0];
        float4 b0 = *(const float4*)&bp0[0];
        float4 b1 = *(const float4*)&bp1[0];
#pragma unroll
        for (int i = 0; i < 4; i++) {
            sA[0][la_k + i][la_r]      = ((const float*)&a0)[i];
            sA[0][la_k + i][la_r + 64] = ((const float*)&a1)[i];
            sB[0][la_k + i][la_r]      = ((const float*)&b0)[i];
            sB[0][la_k + i][la_r + 64] = ((const float*)&b1)[i];
        }
    }
    __syncthreads();

    int buf = 0;
    const int NT = Hh / 16;  // 32
    for (int kt = 0; kt < NT; ++kt) {
        float4 na0, na1, nb0, nb1;
        const bool more = (kt + 1 < NT);
        if (more) {
            const int ko = (kt + 1) * 16;
            na0 = *(const float4*)&ap0[ko];
            na1 = *(const float4*)&ap1[ko];
            nb0 = *(const float4*)&bp0[ko];
            nb1 = *(const float4*)&bp1[ko];
        }
#pragma unroll
        for (int k = 0; k < 16; k++) {
            float4 av0 = *(const float4*)&sA[buf][k][ty * 4];
            float4 av1 = *(const float4*)&sA[buf][k][ty * 4 + 64];
            float4 bv0 = *(const float4*)&sB[buf][k][tx * 4];
            float4 bv1 = *(const float4*)&sB[buf][k][tx * 4 + 64];
            const float a[8] = {av0.x, av0.y, av0.z, av0.w, av1.x, av1.y, av1.z, av1.w};
            const float bvals[8] = {bv0.x, bv0.y, bv0.z, bv0.w, bv1.x, bv1.y, bv1.z, bv1.w};
#pragma unroll
            for (int i = 0; i < 8; i++)
#pragma unroll
                for (int j = 0; j < 8; j++)
                    acc[i][j] = fmaf(a[i], bvals[j], acc[i][j]);
        }
        if (more) {
            int nbuf = buf ^ 1;
#pragma unroll
            for (int i = 0; i < 4; i++) {
                sA[nbuf][la_k + i][la_r]      = ((const float*)&na0)[i];
                sA[nbuf][la_k + i][la_r + 64] = ((const float*)&na1)[i];
                sB[nbuf][la_k + i][la_r]      = ((const float*)&nb0)[i];
                sB[nbuf][la_k + i][la_r + 64] = ((const float*)&nb1)[i];
            }
            __syncthreads();
            buf = nbuf;
        }
    }

#pragma unroll
    for (int i = 0; i < 8; i++) {
        const int m = bm0 + ((i >> 2) * 64) + ty * 4 + (i & 3);
        float* orow = out + (size_t)m * Vv + bn0;
#pragma unroll
        for (int js = 0; js < 2; js++) {
            const int n = js * 64 + tx * 4;
            const float4 bb = *(const float4*)&b_out[bn0 + n];
            float4 r;
            r.x = acc[i][js * 4 + 0] + bb.x;
            r.y = acc[i][js * 4 + 1] + bb.y;
            r.z = acc[i][js * 4 + 2] + bb.z;
            r.w = acc[i][js * 4 + 3] + bb.w;
            *(float4*)&orow[n] = r;
        }
    }
}

// ---------------- Kernel D: in-place log_softmax per row ----------------
__device__ __forceinline__ float fexp_fast(float x) {
    float t = x * 1.4426950408889634f;
    t = fmaxf(t, -126.f);
    float r = rintf(t);
    float f = t - r;
    float p = 1.3333558e-3f;
    p = fmaf(p, f, 9.6181291e-3f);
    p = fmaf(p, f, 5.5504109e-2f);
    p = fmaf(p, f, 2.4022651e-1f);
    p = fmaf(p, f, 6.9314718e-1f);
    p = fmaf(p, f, 1.0f);
    float sc = __int_as_float(((int)r + 127) << 23);
    return p * sc;
}

__global__ void __launch_bounds__(256) softmax_kernel(float* __restrict__ out) {
    extern __shared__ float srow[];   // Vv floats = 128000 B
    __shared__ float sred[256];
    __shared__ float s_lse;
    const int tid = threadIdx.x;
    float* rowp = out + (size_t)blockIdx.x * Vv;

    float mx = -3.4e38f;
    for (int i = tid; i < Vv / 4; i += 256) {
        float4 v = *(const float4*)&rowp[i * 4];
        *(float4*)&srow[i * 4] = v;
        mx = fmaxf(mx, fmaxf(fmaxf(v.x, v.y), fmaxf(v.z, v.w)));
    }
    sred[tid] = mx;
    __syncthreads();
    for (int off = 128; off > 0; off >>= 1) {
        if (tid < off) sred[tid] = fmaxf(sred[tid], sred[tid + off]);
        __syncthreads();
    }
    const float rmax = sred[0];
    __syncthreads();

    float sum = 0.f;
    for (int i = tid; i < Vv / 4; i += 256) {
        float4 v = *(const float4*)&srow[i * 4];
        sum += fexp_fast(v.x - rmax) + fexp_fast(v.y - rmax)
             + fexp_fast(v.z - rmax) + fexp_fast(v.w - rmax);
    }
    sred[tid] = sum;
    __syncthreads();
    for (int off = 128; off > 0; off >>= 1) {
        if (tid < off) sred[tid] += sred[tid + off];
        __syncthreads();
    }
    if (tid == 0) s_lse = rmax + logf(sred[0]);
    __syncthreads();
    const float lse = s_lse;

    for (int i = tid; i < Vv / 4; i += 256) {
        float4 v = *(const float4*)&srow[i * 4];
        v.x -= lse; v.y -= lse; v.z -= lse; v.w -= lse;
        *(float4*)&rowp[i * 4] = v;
    }
}

// ---------------- launch ----------------
extern "C" void kernel_launch(void* const* d_in, const int* in_sizes, int n_in,
                              void* d_out, int out_size) {
    const int*   tseq    = (const int*)d_in[0];
    const float* thought = (const float*)d_in[1];
    const float* hidden  = (const float*)d_in[2];
    const float* emb     = (const float*)d_in[3];
    const float* W_ih    = (const float*)d_in[4];
    const float* W_hh    = (const float*)d_in[5];
    const float* b_ih    = (const float*)d_in[6];
    const float* b_hh    = (const float*)d_in[7];
    const float* W_out   = (const float*)d_in[8];
    const float* b_out   = (const float*)d_in[9];

    float* out  = (float*)d_out;
    float* outH = out + (size_t)Bb * Ss * Vv;   // hidden tail

    const int gru_smem = (6144 + 8256 + 768) * 4;   // 60672 B
    cudaFuncSetAttribute(gru_kernel, cudaFuncAttributeMaxDynamicSharedMemorySize, gru_smem);
    cudaFuncSetAttribute(softmax_kernel, cudaFuncAttributeMaxDynamicSharedMemorySize, Vv * 4);

    dim3 gA(1024 / 64, G3 / 64);        // 16 x 24
    gi_gemm<<<gA, 256>>>(tseq, thought, emb, W_ih, b_ih);

    gru_kernel<<<NCTA_GRU, 256, gru_smem>>>(hidden, W_hh, b_hh, outH);

    dim3 gC(Vv / 128, 1024 / 128);      // 250 x 8
    out_gemm<<<gC, 256>>>(W_out, b_out, out);

    softmax_kernel<<<Bb * Ss, 256, Vv * 4>>>(out);

    (void)in_sizes; (void)n_in; (void)out_size;
}

// round 17
// speedup vs baseline: 1.4743x; 1.4743x over previous
#include <cuda_runtime.h>
#include <cstdint>
#include <math.h>

#define Vv 32000
#define Hh 512
#define Bb 16
#define Ss 64
#define G3 1536   // 3H
#define K2 1024   // 2H
#define NCTA_GRU 128

// ---------------- scratch (static device allocations only) ----------------
__device__ __align__(16) float g_gi[Ss * Bb * G3];      // [s][b][3H]
__device__ __align__(16) float g_ys[Ss * Bb * Hh];      // [s][b][H]
__device__ __align__(16) float g_h[2][Bb * Hh];         // double-buffered h
__device__ unsigned long long g_slots[NCTA_GRU];        // barrier slots (monotonic)

__device__ __forceinline__ unsigned long long ld_slot(const unsigned long long* p) {
    unsigned long long v;
    asm volatile("ld.global.cg.u64 %0, [%1];" : "=l"(v) : "l"(p) : "memory");
    return v;
}

__device__ __forceinline__ float4 ldcg4(const float* p) {
    float4 v;
    asm volatile("ld.global.cg.v4.f32 {%0,%1,%2,%3}, [%4];"
                 : "=f"(v.x), "=f"(v.y), "=f"(v.z), "=f"(v.w) : "l"(p));
    return v;
}

// TF32 rounding (matches cublas tf32 input rounding, round-to-nearest).
__device__ __forceinline__ float tf32r(float x) {
    uint32_t u;
    asm("cvt.rna.tf32.f32 %0, %1;" : "=r"(u) : "f"(x));
    return __uint_as_float(u);
}
__device__ __forceinline__ float4 tf32r4(float4 v) {
    v.x = tf32r(v.x); v.y = tf32r(v.y); v.z = tf32r(v.z); v.w = tf32r(v.w);
    return v;
}

// cp.async helpers
__device__ __forceinline__ void cpa16(uint32_t dst, const void* src) {
    asm volatile("cp.async.ca.shared.global [%0], [%1], 16;" :: "r"(dst), "l"(src));
}
__device__ __forceinline__ void cpa_commit() { asm volatile("cp.async.commit_group;"); }
template <int N> __device__ __forceinline__ void cpa_wait() {
    asm volatile("cp.async.wait_group %0;" :: "n"(N));
}

// ---------------- Kernel A: gi = concat(emb[tok], thought) @ W_ih^T + b_ih ----------------
// FROZEN: byte-identical to the round-6 PASSING kernel (tf32 input semantics).
__global__ void __launch_bounds__(256) gi_gemm(const int* __restrict__ tseq,
                                               const float* __restrict__ thought,
                                               const float* __restrict__ emb,
                                               const float* __restrict__ W_ih,
                                               const float* __restrict__ b_ih) {
    __shared__ float sA[2][16][64];
    __shared__ float sB[2][16][64];
    const int tid = threadIdx.x;
    const int bm0 = blockIdx.x * 64, bn0 = blockIdx.y * 64;
    const int tx = tid & 15, ty = tid >> 4;
    const int la_m = tid >> 2, la_k = (tid & 3) * 4;

    const int am = bm0 + la_m;
    const int s_ = am >> 4, b_ = am & 15;           // row = s*16+b
    const int tok = tseq[b_ * Ss + s_];
    const float* __restrict__ arow0 = emb + (size_t)tok * Hh;
    const float* __restrict__ arow1 = thought + (size_t)b_ * Hh;
    const float* __restrict__ brow  = W_ih + (size_t)(bn0 + la_m) * K2 + la_k;

    float acc[4][4];
#pragma unroll
    for (int i = 0; i < 4; i++)
#pragma unroll
        for (int j = 0; j < 4; j++) acc[i][j] = 0.f;

    {
        int kg = la_k;
        float4 a4 = tf32r4((kg < Hh) ? *(const float4*)&arow0[kg] : *(const float4*)&arow1[kg - Hh]);
        float4 b4 = tf32r4(*(const float4*)&brow[0]);
        sA[0][la_k + 0][la_m] = a4.x; sA[0][la_k + 1][la_m] = a4.y;
        sA[0][la_k + 2][la_m] = a4.z; sA[0][la_k + 3][la_m] = a4.w;
        sB[0][la_k + 0][la_m] = b4.x; sB[0][la_k + 1][la_m] = b4.y;
        sB[0][la_k + 2][la_m] = b4.z; sB[0][la_k + 3][la_m] = b4.w;
    }
    __syncthreads();

    int buf = 0;
    const int NT = K2 / 16;  // 64
    for (int kt = 0; kt < NT; ++kt) {
        float4 na, nb;
        const bool more = (kt + 1 < NT);
        if (more) {
            int kg = (kt + 1) * 16 + la_k;
            na = (kg < Hh) ? *(const float4*)&arow0[kg] : *(const float4*)&arow1[kg - Hh];
            nb = *(const float4*)&brow[(kt + 1) * 16];
        }
#pragma unroll
        for (int k = 0; k < 16; k++) {
            float4 av = *(const float4*)&sA[buf][k][ty * 4];
            float4 bv = *(const float4*)&sB[buf][k][tx * 4];
            acc[0][0] = fmaf(av.x, bv.x, acc[0][0]); acc[0][1] = fmaf(av.x, bv.y, acc[0][1]);
            acc[0][2] = fmaf(av.x, bv.z, acc[0][2]); acc[0][3] = fmaf(av.x, bv.w, acc[0][3]);
            acc[1][0] = fmaf(av.y, bv.x, acc[1][0]); acc[1][1] = fmaf(av.y, bv.y, acc[1][1]);
            acc[1][2] = fmaf(av.y, bv.z, acc[1][2]); acc[1][3] = fmaf(av.y, bv.w, acc[1][3]);
            acc[2][0] = fmaf(av.z, bv.x, acc[2][0]); acc[2][1] = fmaf(av.z, bv.y, acc[2][1]);
            acc[2][2] = fmaf(av.z, bv.z, acc[2][2]); acc[2][3] = fmaf(av.z, bv.w, acc[2][3]);
            acc[3][0] = fmaf(av.w, bv.x, acc[3][0]); acc[3][1] = fmaf(av.w, bv.y, acc[3][1]);
            acc[3][2] = fmaf(av.w, bv.z, acc[3][2]); acc[3][3] = fmaf(av.w, bv.w, acc[3][3]);
        }
        if (more) {
            int nbuf = buf ^ 1;
            na = tf32r4(na); nb = tf32r4(nb);
            sA[nbuf][la_k + 0][la_m] = na.x; sA[nbuf][la_k + 1][la_m] = na.y;
            sA[nbuf][la_k + 2][la_m] = na.z; sA[nbuf][la_k + 3][la_m] = na.w;
            sB[nbuf][la_k + 0][la_m] = nb.x; sB[nbuf][la_k + 1][la_m] = nb.y;
            sB[nbuf][la_k + 2][la_m] = nb.z; sB[nbuf][la_k + 3][la_m] = nb.w;
            __syncthreads();
            buf = nbuf;
        }
    }

    const float4 bb = *(const float4*)&b_ih[bn0 + tx * 4];
#pragma unroll
    for (int i = 0; i < 4; i++) {
        float4 r;
        r.x = acc[i][0] + bb.x; r.y = acc[i][1] + bb.y;
        r.z = acc[i][2] + bb.z; r.w = acc[i][3] + bb.w;
        *(float4*)&g_gi[(size_t)(bm0 + ty * 4 + i) * G3 + bn0 + tx * 4] = r;
    }
}

// ---------------- Kernel B: persistent GRU over 64 steps ----------------
// FROZEN: byte-identical to the round-6 PASSING kernel (tf32 dot inputs,
// fp32 carry).
__global__ void __launch_bounds__(256) gru_kernel(const float* __restrict__ hidden,
                                                  const float* __restrict__ W_hh,
                                                  const float* __restrict__ b_hh,
                                                  float* __restrict__ outH) {
    extern __shared__ float smem[];
    float* sW  = smem;                 // [3][4][512]
    float* sh  = smem + 6144;          // [16][516]
    float* red = smem + 6144 + 8256;   // [3][4][16][4]

    const int tid = threadIdx.x;
    const int cta = blockIdx.x;
    const int j0 = cta * 4;

    __shared__ unsigned long long sbase;
    if (tid == 0) sbase = g_slots[cta];

    for (int i = tid; i < 6144 / 4; i += 256) {
        int f = i * 4;
        int g = f >> 11; int jj = (f >> 9) & 3; int k = f & 511;
        float4 w = tf32r4(*(const float4*)&W_hh[(size_t)(g * Hh + j0 + jj) * Hh + k]);
        *(float4*)&sW[(g * 4 + jj) * 512 + k] = w;
    }
    __syncthreads();

    const int lane = tid & 31, wrp = tid >> 5;
    const int jj  = wrp & 3;
    const int ks  = (((wrp >> 2) << 1) | (lane >> 4));  // 0..3
    const int b   = lane & 15;
    const int kb  = ks * 128;
    const float* wr = &sW[(0 * 4 + jj) * 512];
    const float* wz = &sW[(1 * 4 + jj) * 512];
    const float* wn = &sW[(2 * 4 + jj) * 512];

    for (int s = 0; s < Ss; s++) {
        const float* hsrc = (s == 0) ? hidden : g_h[(s + 1) & 1];
        for (int i = tid; i < 2048; i += 256) {
            int f = i * 4; int bb2 = f >> 9; int k = f & 511;
            float4 hv = ldcg4(&hsrc[bb2 * Hh + k]);
            *(float4*)&sh[bb2 * 516 + k] = hv;
        }
        __syncthreads();

        float ar = 0.f, az = 0.f, an = 0.f;
        const float* hb = &sh[b * 516];
#pragma unroll 8
        for (int k = kb; k < kb + 128; k += 4) {
            float4 hv = tf32r4(*(const float4*)&hb[k]);
            float4 r4 = *(const float4*)&wr[k];
            float4 z4 = *(const float4*)&wz[k];
            float4 n4 = *(const float4*)&wn[k];
            ar = fmaf(hv.x, r4.x, ar); ar = fmaf(hv.y, r4.y, ar);
            ar = fmaf(hv.z, r4.z, ar); ar = fmaf(hv.w, r4.w, ar);
            az = fmaf(hv.x, z4.x, az); az = fmaf(hv.y, z4.y, az);
            az = fmaf(hv.z, z4.z, az); az = fmaf(hv.w, z4.w, az);
            an = fmaf(hv.x, n4.x, an); an = fmaf(hv.y, n4.y, an);
            an = fmaf(hv.z, n4.z, an); an = fmaf(hv.w, n4.w, an);
        }
        red[((0 * 4 + jj) * 16 + b) * 4 + ks] = ar;
        red[((1 * 4 + jj) * 16 + b) * 4 + ks] = az;
        red[((2 * 4 + jj) * 16 + b) * 4 + ks] = an;
        __syncthreads();

        if (tid < 64) {
            const int jj2 = tid >> 4, b2 = tid & 15;
            const int col = j0 + jj2;
            float ghr = 0.f, ghz = 0.f, ghn = 0.f;
#pragma unroll
            for (int q = 0; q < 4; q++) {
                ghr += red[((0 * 4 + jj2) * 16 + b2) * 4 + q];
                ghz += red[((1 * 4 + jj2) * 16 + b2) * 4 + q];
                ghn += red[((2 * 4 + jj2) * 16 + b2) * 4 + q];
            }
            ghr += __ldg(&b_hh[col]); ghz += __ldg(&b_hh[Hh + col]); ghn += __ldg(&b_hh[2 * Hh + col]);
            const size_t gib = (size_t)(s * Bb + b2) * G3 + col;
            const float ir = g_gi[gib], iz = g_gi[gib + Hh], inn = g_gi[gib + 2 * Hh];
            const float r = 1.f / (1.f + expf(-(ir + ghr)));
            const float z = 1.f / (1.f + expf(-(iz + ghz)));
            const float n = tanhf(inn + r * ghn);
            const float ho = sh[b2 * 516 + col];
            const float hn = (1.f - z) * n + z * ho;
            g_h[s & 1][b2 * Hh + col] = hn;
            g_ys[(size_t)(s * Bb + b2) * Hh + col] = hn;
            if (s == Ss - 1) outH[b2 * Hh + col] = hn;
        }
        __syncthreads();

        if (s < Ss - 1) {
            const unsigned long long tgt = sbase + (unsigned long long)(s + 1);
            if (tid == 0) {
                __threadfence();
                ((volatile unsigned long long*)g_slots)[cta] = tgt;
            }
            if (tid < 32) {
                for (;;) {
                    bool ok = true;
#pragma unroll
                    for (int q = 0; q < 4; q++)
                        ok &= (ld_slot(&g_slots[lane + q * 32]) >= tgt);
                    if (ok) break;
                }
            }
            __syncthreads();
        }
    }
}

// ---------------- Kernel C: logits GEMM on tensor cores (mma.sync tf32) ----------------
// Fragments RNA-rounded to tf32 before mma (matches cublas rounding).
#define OS_STRIDE 36
#define OS_BUF (128 * OS_STRIDE)

__device__ __forceinline__ void mma_tf32(float* d, const float* a, const float* b) {
    asm volatile(
        "mma.sync.aligned.m16n8k8.row.col.f32.tf32.tf32.f32 "
        "{%0,%1,%2,%3}, {%4,%5,%6,%7}, {%8,%9}, {%0,%1,%2,%3};"
        : "+f"(d[0]), "+f"(d[1]), "+f"(d[2]), "+f"(d[3])
        : "r"(__float_as_uint(a[0])), "r"(__float_as_uint(a[1])),
          "r"(__float_as_uint(a[2])), "r"(__float_as_uint(a[3])),
          "r"(__float_as_uint(b[0])), "r"(__float_as_uint(b[1])));
}

__global__ void __launch_bounds__(256) out_gemm_mma(const float* __restrict__ W_out,
                                                    const float* __restrict__ b_out,
                                                    float* __restrict__ out) {
    extern __shared__ float osm[];
    float* sA = osm;                  // [2][128][36]
    float* sB = osm + 2 * OS_BUF;     // [2][128][36]

    const int tid = threadIdx.x;
    const int bn0 = blockIdx.x * 128, bm0 = blockIdx.y * 128;
    const int lane = tid & 31, wid = tid >> 5;
    const int wm = wid >> 2, wn = wid & 3;
    const int gid = lane >> 2, qid = lane & 3;

    float acc[4][4][4];
#pragma unroll
    for (int mf = 0; mf < 4; mf++)
#pragma unroll
        for (int nf = 0; nf < 4; nf++)
#pragma unroll
            for (int rr = 0; rr < 4; rr++) acc[mf][nf][rr] = 0.f;

    const int r = tid >> 1, half = tid & 1;
    const int gm = bm0 + r;
    const int srow = (gm & 63) * Bb + (gm >> 6);
    const float* aptr = g_ys + (size_t)srow * Hh + half * 16;
    const float* bptr = W_out + (size_t)(bn0 + r) * Hh + half * 16;
    const uint32_t saw = (uint32_t)__cvta_generic_to_shared(sA) + (r * OS_STRIDE + half * 16) * 4;
    const uint32_t sbw = (uint32_t)__cvta_generic_to_shared(sB) + (r * OS_STRIDE + half * 16) * 4;

#define OS_STAGE(BUF, KT) do {                                              \
        const float* as_ = aptr + (KT) * 32;                                \
        const float* bs_ = bptr + (KT) * 32;                                \
        const uint32_t da_ = saw + (BUF) * OS_BUF * 4;                      \
        const uint32_t db_ = sbw + (BUF) * OS_BUF * 4;                      \
        cpa16(da_ +  0, as_ +  0); cpa16(db_ +  0, bs_ +  0);               \
        cpa16(da_ + 16, as_ +  4); cpa16(db_ + 16, bs_ +  4);               \
        cpa16(da_ + 32, as_ +  8); cpa16(db_ + 32, bs_ +  8);               \
        cpa16(da_ + 48, as_ + 12); cpa16(db_ + 48, bs_ + 12);               \
    } while (0)

    OS_STAGE(0, 0);
    cpa_commit();

    const int NT = Hh / 32;  // 16
    for (int kt = 0; kt < NT; ++kt) {
        const int buf = kt & 1;
        if (kt + 1 < NT) {
            OS_STAGE(buf ^ 1, kt + 1);
            cpa_commit();
            cpa_wait<1>();
        } else {
            cpa_wait<0>();
        }
        __syncthreads();

        const float* A = sA + buf * OS_BUF;
        const float* B = sB + buf * OS_BUF;
#pragma unroll
        for (int ks = 0; ks < 4; ks++) {
            float afr[4][4];
#pragma unroll
            for (int mf = 0; mf < 4; mf++) {
                const float* ap = A + (wm * 64 + mf * 16 + gid) * OS_STRIDE + ks * 8 + qid;
                afr[mf][0] = tf32r(ap[0]);
                afr[mf][1] = tf32r(ap[8 * OS_STRIDE]);
                afr[mf][2] = tf32r(ap[4]);
                afr[mf][3] = tf32r(ap[8 * OS_STRIDE + 4]);
            }
            float bfr[4][2];
#pragma unroll
            for (int nf = 0; nf < 4; nf++) {
                const float* bp = B + (wn * 32 + nf * 8 + gid) * OS_STRIDE + ks * 8 + qid;
                bfr[nf][0] = tf32r(bp[0]);
                bfr[nf][1] = tf32r(bp[4]);
            }
#pragma unroll
            for (int mf = 0; mf < 4; mf++)
#pragma unroll
                for (int nf = 0; nf < 4; nf++)
                    mma_tf32(acc[mf][nf], afr[mf], bfr[nf]);
        }
        __syncthreads();
    }

#pragma unroll
    for (int mf = 0; mf < 4; mf++) {
        const int mA = bm0 + wm * 64 + mf * 16 + gid;
        const int mB = mA + 8;
#pragma unroll
        for (int nf = 0; nf < 4; nf++) {
            const int n = bn0 + wn * 32 + nf * 8 + 2 * qid;
            const float2 bb = *(const float2*)&b_out[n];
            float2 v0, v1;
            v0.x = acc[mf][nf][0] + bb.x; v0.y = acc[mf][nf][1] + bb.y;
            v1.x = acc[mf][nf][2] + bb.x; v1.y = acc[mf][nf][3] + bb.y;
            *(float2*)&out[(size_t)mA * Vv + n] = v0;
            *(float2*)&out[(size_t)mB * Vv + n] = v1;
        }
    }
}

// ---------------- Kernel D: log_softmax, streaming 3-pass ----------------
__device__ __forceinline__ float fexp_fast(float x) {
    float t = x * 1.4426950408889634f;
    t = fmaxf(t, -126.f);
    float r = rintf(t);
    float f = t - r;
    float p = 1.3333558e-3f;
    p = fmaf(p, f, 9.6181291e-3f);
    p = fmaf(p, f, 5.5504109e-2f);
    p = fmaf(p, f, 2.4022651e-1f);
    p = fmaf(p, f, 6.9314718e-1f);
    p = fmaf(p, f, 1.0f);
    float sc = __int_as_float(((int)r + 127) << 23);
    return p * sc;
}

__global__ void __launch_bounds__(256) softmax_kernel(float* __restrict__ out) {
    __shared__ float sred[256];
    __shared__ float s_lse;
    const int tid = threadIdx.x;
    float* rowp = out + (size_t)blockIdx.x * Vv;

    float mx = -3.4e38f;
    for (int i = tid; i < Vv / 4; i += 256) {
        float4 v = *(const float4*)&rowp[i * 4];
        mx = fmaxf(mx, fmaxf(fmaxf(v.x, v.y), fmaxf(v.z, v.w)));
    }
    sred[tid] = mx;
    __syncthreads();
    for (int off = 128; off > 0; off >>= 1) {
        if (tid < off) sred[tid] = fmaxf(sred[tid], sred[tid + off]);
        __syncthreads();
    }
    const float rmax = sred[0];
    __syncthreads();

    float sum = 0.f;
    for (int i = tid; i < Vv / 4; i += 256) {
        float4 v = *(const float4*)&rowp[i * 4];
        sum += fexp_fast(v.x - rmax) + fexp_fast(v.y - rmax)
             + fexp_fast(v.z - rmax) + fexp_fast(v.w - rmax);
    }
    sred[tid] = sum;
    __syncthreads();
    for (int off = 128; off > 0; off >>= 1) {
        if (tid < off) sred[tid] += sred[tid + off];
        __syncthreads();
    }
    if (tid == 0) s_lse = rmax + logf(sred[0]);
    __syncthreads();
    const float lse = s_lse;

    for (int i = tid; i < Vv / 4; i += 256) {
        float4 v = *(const float4*)&rowp[i * 4];
        v.x -= lse; v.y -= lse; v.z -= lse; v.w -= lse;
        *(float4*)&rowp[i * 4] = v;
    }
}

// ---------------- launch ----------------
extern "C" void kernel_launch(void* const* d_in, const int* in_sizes, int n_in,
                              void* d_out, int out_size) {
    const int*   tseq    = (const int*)d_in[0];
    const float* thought = (const float*)d_in[1];
    const float* hidden  = (const float*)d_in[2];
    const float* emb     = (const float*)d_in[3];
    const float* W_ih    = (const float*)d_in[4];
    const float* W_hh    = (const float*)d_in[5];
    const float* b_ih    = (const float*)d_in[6];
    const float* b_hh    = (const float*)d_in[7];
    const float* W_out   = (const float*)d_in[8];
    const float* b_out   = (const float*)d_in[9];

    float* out  = (float*)d_out;
    float* outH = out + (size_t)Bb * Ss * Vv;   // hidden tail

    const int gru_smem = (6144 + 8256 + 768) * 4;        // 60672 B
    const int gem_smem = 4 * OS_BUF * 4;                  // 73728 B
    cudaFuncSetAttribute(gru_kernel, cudaFuncAttributeMaxDynamicSharedMemorySize, gru_smem);
    cudaFuncSetAttribute(out_gemm_mma, cudaFuncAttributeMaxDynamicSharedMemorySize, gem_smem);

    dim3 gA(1024 / 64, G3 / 64);        // 16 x 24
    gi_gemm<<<gA, 256>>>(tseq, thought, emb, W_ih, b_ih);

    gru_kernel<<<NCTA_GRU, 256, gru_smem>>>(hidden, W_hh, b_hh, outH);

    dim3 gC(Vv / 128, 1024 / 128);      // 250 x 8
    out_gemm_mma<<<gC, 256, gem_smem>>>(W_out, b_out, out);

    softmax_kernel<<<Bb * Ss, 256>>>(out);

    (void)in_sizes; (void)n_in; (void)out_size;
}